// round 13
// baseline (speedup 1.0000x reference)
#include <cuda_runtime.h>
#include <cstdint>

#define FULL_MASK 0xFFFFFFFFu
#define NQ 8
#define DEPTH 3
#define FDIM 512
#define NCLS 10
#define PTHREADS 128
#define CTHREADS 64
#define MAXB 8192

typedef unsigned long long u64;

// ---- device-global scratch (allocation-free) ----
__device__ float2 g_cs[MAXB * NQ];      // (cos, sin) of half-angle per (b, q)
__device__ float4 g_gates[DEPTH * NQ][2];

// ---- packed f32x2 helpers ----
__device__ __forceinline__ u64 pk2(float lo, float hi) {
    u64 r; asm("mov.b64 %0,{%1,%2};" : "=l"(r) : "f"(lo), "f"(hi)); return r;
}
__device__ __forceinline__ void up2(u64 v, float& lo, float& hi) {
    asm("mov.b64 {%0,%1},%2;" : "=f"(lo), "=f"(hi) : "l"(v));
}
__device__ __forceinline__ u64 fma2_(u64 a, u64 b, u64 c) {
    u64 d; asm("fma.rn.f32x2 %0,%1,%2,%3;" : "=l"(d) : "l"(a), "l"(b), "l"(c)); return d;
}
__device__ __forceinline__ u64 mul2_(u64 a, u64 b) {
    u64 d; asm("mul.rn.f32x2 %0,%1,%2;" : "=l"(d) : "l"(a), "l"(b)); return d;
}
__device__ __forceinline__ u64 add2_(u64 a, u64 b) {
    u64 d; asm("add.rn.f32x2 %0,%1,%2;" : "=l"(d) : "l"(a), "l"(b)); return d;
}
__device__ __forceinline__ u64 neg2_(u64 a) { return a ^ 0x8000000080000000ULL; }
__device__ __forceinline__ u64 bc2(float c) { return pk2(c, c); }

// ============================================================
// Kernel 1: projection + tanh + half-angle sincos -> g_cs ; gates -> g_gates
// (unchanged - proven)
// ============================================================
__global__ void __launch_bounds__(PTHREADS, 8) proj_kernel(
    const float* __restrict__ x,
    const float* __restrict__ proj_w,
    const float* __restrict__ qnn_w,
    int B)
{
    const int tid  = threadIdx.x;
    const int lane = tid & 31;
    const int warp = tid >> 5;

    if (blockIdx.x == 0 && tid < DEPTH * NQ) {
        float w0 = qnn_w[tid * 3 + 0];
        float w1 = qnn_w[tid * 3 + 1];
        float w2 = qnn_w[tid * 3 + 2];
        float c0, s0, c1, s1, c2, s2;
        sincosf(0.5f * w0, &s0, &c0);
        sincosf(0.5f * w1, &s1, &c1);
        sincosf(0.5f * w2, &s2, &c2);
        float2 A00 = { c1 * c0,  s1 * s0};
        float2 A01 = {-s1 * c0, -c1 * s0};
        float2 A10 = { s1 * c0, -c1 * s0};
        float2 A11 = { c1 * c0, -s1 * s0};
        float2 q00 = make_float2(c2 * A00.x + s2 * A10.y, c2 * A00.y - s2 * A10.x);
        float2 q01 = make_float2(c2 * A01.x + s2 * A11.y, c2 * A01.y - s2 * A11.x);
        float2 q10 = make_float2(c2 * A10.x + s2 * A00.y, c2 * A10.y - s2 * A00.x);
        float2 q11 = make_float2(c2 * A11.x + s2 * A01.y, c2 * A11.y - s2 * A01.x);
        g_gates[tid][0] = make_float4(q00.x, q00.y, q01.x, q01.y);
        g_gates[tid][1] = make_float4(q10.x, q10.y, q11.x, q11.y);
    }

    const int b0 = (blockIdx.x * 4 + warp) * 2;
    const int b1 = b0 + 1;
    if (b0 >= B) return;
    const bool v1 = (b1 < B);

    float acc[2][NQ];
    #pragma unroll
    for (int e = 0; e < 2; e++)
        #pragma unroll
        for (int q = 0; q < NQ; q++) acc[e][q] = 0.f;

    const float4* xr0 = (const float4*)(x + (size_t)b0 * FDIM);
    const float4* xr1 = (const float4*)(x + (size_t)(v1 ? b1 : b0) * FDIM);
    #pragma unroll
    for (int ch = 0; ch < 4; ch++) {
        float4 xv0 = xr0[ch * 32 + lane];
        float4 xv1 = xr1[ch * 32 + lane];
        #pragma unroll
        for (int q = 0; q < NQ; q++) {
            float4 wv = __ldg((const float4*)&proj_w[q * FDIM + ch * 128 + lane * 4]);
            acc[0][q] += xv0.x*wv.x + xv0.y*wv.y + xv0.z*wv.z + xv0.w*wv.w;
            acc[1][q] += xv1.x*wv.x + xv1.y*wv.y + xv1.z*wv.z + xv1.w*wv.w;
        }
    }
    auto mrgP = [&](u64 a, u64 b, int dist) -> u64 {
        u64 c = (lane & dist) ? b : a;
        u64 d = (lane & dist) ? a : b;
        return add2_(c, __shfl_xor_sync(FULL_MASK, d, dist));
    };
    u64 ap[8];
    #pragma unroll
    for (int q = 0; q < NQ; q++) ap[q] = pk2(acc[0][q], acc[1][q]);
    u64 m0 = mrgP(ap[0], ap[1], 16), m1 = mrgP(ap[2], ap[3], 16);
    u64 m2 = mrgP(ap[4], ap[5], 16), m3 = mrgP(ap[6], ap[7], 16);
    u64 n0 = mrgP(m0, m1, 8), n1 = mrgP(m2, m3, 8);
    u64 F  = mrgP(n0, n1, 4);
    F = add2_(F, __shfl_xor_sync(FULL_MASK, F, 2));
    F = add2_(F, __shfl_xor_sync(FULL_MASK, F, 1));

    if ((lane & 3) == 0) {
        const int q = ((lane >> 4) & 1) | (((lane >> 3) & 1) << 1) | (((lane >> 2) & 1) << 2);
        float dA, dB; up2(F, dA, dB);
        float hA = tanhf(dA) * 0.78539816339744830962f;
        float hB = tanhf(dB) * 0.78539816339744830962f;
        float cA, sA, cB, sB;
        __sincosf(hA, &sA, &cA);
        __sincosf(hB, &sB, &cB);
        g_cs[b0 * NQ + q] = make_float2(cA, sA);
        if (v1) g_cs[b1 * NQ + q] = make_float2(cB, sB);
    }
}

// ============================================================
// Kernel 2: circuit — batch-packed f32x2 (R10-proven), 64-thr blocks
// Deferred-CNOT masks (GF(2)); layout p = (lane<<3)|r.
// parity table for 3-bit values: 0x96
// ============================================================
template<int PM, int W>
__device__ __forceinline__ void gateP(u64 AR[8], u64 AI[8], float4 A, float4 Bv, int lane)
{
    constexpr int pr = PM & 7, pl = PM >> 3, wr = W & 7, wl = W >> 3;
    bool bL = (wl != 0) && ((__popc(lane & wl) & 1) != 0);
    u64 oAx2 = bc2(bL ? Bv.z : A.x), oAy2 = bc2(bL ? Bv.w : A.y);
    u64 pAx2 = bc2(bL ? Bv.x : A.z), pAy2 = bc2(bL ? Bv.y : A.w);
    u64 oBx2 = bc2(bL ? A.x : Bv.z), oBy2 = bc2(bL ? A.y : Bv.w);
    u64 pBx2 = bc2(bL ? A.z : Bv.x), pBy2 = bc2(bL ? A.w : Bv.y);

    if constexpr (pl == 0) {
        #pragma unroll
        for (int r = 0; r < 8; r++) {
            if (((0x96 >> (r & wr)) & 1) == 0) {
                const int r1 = r ^ pr;
                u64 a0r = AR[r], a0i = AI[r], a1r = AR[r1], a1i = AI[r1];
                AR[r]  = fma2_(neg2_(pAy2), a1i, fma2_(pAx2, a1r, fma2_(neg2_(oAy2), a0i, mul2_(oAx2, a0r))));
                AI[r]  = fma2_(pAy2, a1r, fma2_(pAx2, a1i, fma2_(oAy2, a0r, mul2_(oAx2, a0i))));
                AR[r1] = fma2_(neg2_(pBy2), a0i, fma2_(pBx2, a0r, fma2_(neg2_(oBy2), a1i, mul2_(oBx2, a1r))));
                AI[r1] = fma2_(pBy2, a0r, fma2_(pBx2, a0i, fma2_(oBy2, a1r, mul2_(oBx2, a1i))));
            }
        }
    } else if constexpr (pr == 0) {
        #pragma unroll
        for (int r = 0; r < 8; r++) {
            u64 tr = __shfl_xor_sync(FULL_MASK, AR[r], pl);
            u64 ti = __shfl_xor_sync(FULL_MASK, AI[r], pl);
            const bool pb = ((0x96 >> (r & wr)) & 1) != 0;
            u64 ox = pb ? oBx2 : oAx2, oy = pb ? oBy2 : oAy2;
            u64 px = pb ? pBx2 : pAx2, py = pb ? pBy2 : pAy2;
            u64 nr = fma2_(neg2_(py), ti, fma2_(px, tr, fma2_(neg2_(oy), AI[r], mul2_(ox, AR[r]))));
            u64 ni = fma2_(py, tr, fma2_(px, ti, fma2_(oy, AR[r], mul2_(ox, AI[r]))));
            AR[r] = nr; AI[r] = ni;
        }
    } else {
        #pragma unroll
        for (int r = 0; r < 8; r++) {
            if (r < (r ^ pr)) {
                const int r1 = r ^ pr;
                u64 sr0 = __shfl_xor_sync(FULL_MASK, AR[r1], pl);
                u64 si0 = __shfl_xor_sync(FULL_MASK, AI[r1], pl);
                u64 sr1 = __shfl_xor_sync(FULL_MASK, AR[r],  pl);
                u64 si1 = __shfl_xor_sync(FULL_MASK, AI[r],  pl);
                const bool pb0 = ((0x96 >> (r  & wr)) & 1) != 0;
                const bool pb1 = ((0x96 >> (r1 & wr)) & 1) != 0;
                u64 o0x = pb0?oBx2:oAx2, o0y = pb0?oBy2:oAy2;
                u64 p0x = pb0?pBx2:pAx2, p0y = pb0?pBy2:pAy2;
                u64 o1x = pb1?oBx2:oAx2, o1y = pb1?oBy2:oAy2;
                u64 p1x = pb1?pBx2:pAx2, p1y = pb1?pBy2:pAy2;
                u64 nr0 = fma2_(neg2_(p0y), si0, fma2_(p0x, sr0, fma2_(neg2_(o0y), AI[r],  mul2_(o0x, AR[r]))));
                u64 ni0 = fma2_(p0y,  sr0, fma2_(p0x, si0, fma2_(o0y,  AR[r],  mul2_(o0x, AI[r]))));
                u64 nr1 = fma2_(neg2_(p1y), si1, fma2_(p1x, sr1, fma2_(neg2_(o1y), AI[r1], mul2_(o1x, AR[r1]))));
                u64 ni1 = fma2_(p1y,  sr1, fma2_(p1x, si1, fma2_(o1y,  AR[r1], mul2_(o1x, AI[r1]))));
                AR[r] = nr0; AI[r] = ni0; AR[r1] = nr1; AI[r1] = ni1;
            }
        }
    }
}

__global__ void __launch_bounds__(CTHREADS, 16) circuit_kernel(
    const float* __restrict__ out_w,
    const float* __restrict__ out_b,
    float* __restrict__ out,
    int B)
{
    __shared__ float4 s_g4[DEPTH * NQ][2];   // 768 B
    __shared__ float  s_ow[NCLS * NQ];
    __shared__ float  s_ob[NCLS];

    const int tid  = threadIdx.x;
    const int lane = tid & 31;
    const int warp = tid >> 5;

    if (tid < DEPTH * NQ * 2) ((float4*)s_g4)[tid] = ((const float4*)g_gates)[tid];
    for (int i = tid; i < NCLS * NQ; i += CTHREADS) s_ow[i] = out_w[i];
    if (tid < NCLS) s_ob[tid] = out_b[tid];
    __syncthreads();

    auto mrgP = [&](u64 a, u64 b, int dist) -> u64 {
        u64 c = (lane & dist) ? b : a;
        u64 d = (lane & dist) ? a : b;
        return add2_(c, __shfl_xor_sync(FULL_MASK, d, dist));
    };
    auto srcLane = [](int q) { return ((q & 1) << 4) | (((q >> 1) & 1) << 3) | (((q >> 2) & 1) << 2); };

    const int b0 = (blockIdx.x * 2 + warp) * 2;   // elem A (lo half)
    const int b1 = b0 + 1;                        // elem B (hi half)
    if (b0 >= B) return;
    const bool v1 = (b1 < B);

    // half-angle cos/sin for qubit (lane&7), both elems packed
    u64 CV, SV;
    {
        float2 csA = __ldg(&g_cs[b0 * NQ + (lane & 7)]);
        float2 csB = __ldg(&g_cs[(v1 ? b1 : b0) * NQ + (lane & 7)]);
        CV = pk2(csA.x, csB.x);
        SV = pk2(csA.y, csB.y);
    }

    // ---- product state (encoding + layer-0 gates); qubit q's c/s at lane q ----
    u64 Lr = pk2(1.f, 1.f), Li = 0ULL;
    #pragma unroll
    for (int k = 0; k < 5; k++) {
        const int q = k + 3;
        u64 cq = __shfl_sync(FULL_MASK, CV, q);
        u64 sq = __shfl_sync(FULL_MASK, SV, q);
        float4 V = s_g4[q][(lane >> k) & 1];
        u64 wx = fma2_(bc2(V.z), sq, mul2_(bc2(V.x), cq));
        u64 wy = fma2_(bc2(V.w), sq, mul2_(bc2(V.y), cq));
        u64 nLr = fma2_(neg2_(Li), wy, mul2_(Lr, wx));
        u64 nLi = fma2_(Li, wx, mul2_(Lr, wy));
        Lr = nLr; Li = nLi;
    }
    u64 AR[8], AI[8];
    {
        u64 cq = __shfl_sync(FULL_MASK, CV, 0);
        u64 sq = __shfl_sync(FULL_MASK, SV, 0);
        float4 A0 = s_g4[0][0], B0 = s_g4[0][1];
        u64 a0x = fma2_(bc2(A0.z), sq, mul2_(bc2(A0.x), cq));
        u64 a0y = fma2_(bc2(A0.w), sq, mul2_(bc2(A0.y), cq));
        u64 b0x = fma2_(bc2(B0.z), sq, mul2_(bc2(B0.x), cq));
        u64 b0y = fma2_(bc2(B0.w), sq, mul2_(bc2(B0.y), cq));
        AR[0] = fma2_(neg2_(Li), a0y, mul2_(Lr, a0x));  AI[0] = fma2_(Li, a0x, mul2_(Lr, a0y));
        AR[1] = fma2_(neg2_(Li), b0y, mul2_(Lr, b0x));  AI[1] = fma2_(Li, b0x, mul2_(Lr, b0y));
    }
    {
        u64 cq = __shfl_sync(FULL_MASK, CV, 1);
        u64 sq = __shfl_sync(FULL_MASK, SV, 1);
        float4 A1 = s_g4[1][0], B1 = s_g4[1][1];
        u64 a1x = fma2_(bc2(A1.z), sq, mul2_(bc2(A1.x), cq));
        u64 a1y = fma2_(bc2(A1.w), sq, mul2_(bc2(A1.y), cq));
        u64 b1x = fma2_(bc2(B1.z), sq, mul2_(bc2(B1.x), cq));
        u64 b1y = fma2_(bc2(B1.w), sq, mul2_(bc2(B1.y), cq));
        #pragma unroll
        for (int r = 0; r < 2; r++) {
            u64 tr = AR[r], ti = AI[r];
            AR[r + 2] = fma2_(neg2_(b1y), ti, mul2_(tr, b1x));  AI[r + 2] = fma2_(b1y, tr, mul2_(ti, b1x));
            AR[r]     = fma2_(neg2_(a1y), ti, mul2_(tr, a1x));  AI[r]     = fma2_(a1y, tr, mul2_(ti, a1x));
        }
    }
    {
        u64 cq = __shfl_sync(FULL_MASK, CV, 2);
        u64 sq = __shfl_sync(FULL_MASK, SV, 2);
        float4 A2 = s_g4[2][0], B2 = s_g4[2][1];
        u64 a2x = fma2_(bc2(A2.z), sq, mul2_(bc2(A2.x), cq));
        u64 a2y = fma2_(bc2(A2.w), sq, mul2_(bc2(A2.y), cq));
        u64 b2x = fma2_(bc2(B2.z), sq, mul2_(bc2(B2.x), cq));
        u64 b2y = fma2_(bc2(B2.w), sq, mul2_(bc2(B2.y), cq));
        #pragma unroll
        for (int r = 0; r < 4; r++) {
            u64 tr = AR[r], ti = AI[r];
            AR[r + 4] = fma2_(neg2_(b2y), ti, mul2_(tr, b2x));  AI[r + 4] = fma2_(b2y, tr, mul2_(ti, b2x));
            AR[r]     = fma2_(neg2_(a2y), ti, mul2_(tr, a2x));  AI[r]     = fma2_(a2y, tr, mul2_(ti, a2x));
        }
    }

    // ---- layers 1,2 with deferred-CNOT masks ----
    #define GATE(idx, PMv, Wv) gateP<PMv, Wv>(AR, AI, s_g4[idx][0], s_g4[idx][1], lane)
    GATE(8,  0x03, 0xFE); GATE(9,  0x06, 0x03); GATE(10, 0x0C, 0x07); GATE(11, 0x18, 0x0F);
    GATE(12, 0x30, 0x1F); GATE(13, 0x60, 0x3F); GATE(14, 0xC0, 0x7F); GATE(15, 0x83, 0xFF);
    GATE(16, 0x05, 0xAB); GATE(17, 0x0A, 0xFD); GATE(18, 0x14, 0xFA); GATE(19, 0x28, 0xF5);
    GATE(20, 0x50, 0xEA); GATE(21, 0xA0, 0xD5); GATE(22, 0x43, 0xAA); GATE(23, 0x86, 0x55);
    #undef GATE

    // ---- PauliZ via Walsh-Hadamard of |amp|^2 (phi = C^3), packed ----
    u64 S[8];
    #pragma unroll
    for (int r = 0; r < 8; r++) S[r] = fma2_(AI[r], AI[r], mul2_(AR[r], AR[r]));
    #pragma unroll
    for (int st = 0; st < 3; st++) {
        const int d = 1 << st;
        #pragma unroll
        for (int r = 0; r < 8; r++) {
            if (!(r & d)) {
                u64 a = add2_(S[r], S[r + d]);
                u64 b = add2_(S[r], neg2_(S[r + d]));
                S[r] = a; S[r + d] = b;
            }
        }
    }
    auto sgp = [&](int wl, u64 v) -> u64 { return (__popc(lane & wl) & 1) ? neg2_(v) : v; };
    u64 z0 = sgp(0x06, S[2]), z1 = sgp(0x0A, S[6]);
    u64 z2 = sgp(0x15, S[4]), z3 = sgp(0x0B, S[1]);
    u64 z4 = sgp(0x16, S[3]), z5 = sgp(0x0C, S[6]);
    u64 z6 = sgp(0x19, S[4]), z7 = sgp(0x13, S[1]);
    u64 m0 = mrgP(z0, z1, 16), m1 = mrgP(z2, z3, 16);
    u64 m2 = mrgP(z4, z5, 16), m3 = mrgP(z6, z7, 16);
    u64 n0 = mrgP(m0, m1, 8),  n1 = mrgP(m2, m3, 8);
    u64 F  = mrgP(n0, n1, 4);
    F = add2_(F, __shfl_xor_sync(FULL_MASK, F, 2));
    F = add2_(F, __shfl_xor_sync(FULL_MASK, F, 1));
    u64 gq[NQ];
    #pragma unroll
    for (int q = 0; q < NQ; q++) gq[q] = __shfl_sync(FULL_MASK, F, srcLane(q));

    // ---- output head ----
    if (lane < NCLS) {
        float o0 = s_ob[lane], o1 = o0;
        #pragma unroll
        for (int q = 0; q < NQ; q++) {
            float w = s_ow[lane * NQ + q];
            float gA, gB; up2(gq[q], gA, gB);
            o0 += gA * w;
            o1 += gB * w;
        }
        out[(size_t)b0 * NCLS + lane] = o0;
        if (v1) out[(size_t)b1 * NCLS + lane] = o1;
    }
}

extern "C" void kernel_launch(void* const* d_in, const int* in_sizes, int n_in,
                              void* d_out, int out_size) {
    const float* x      = (const float*)d_in[0];
    const float* proj_w = (const float*)d_in[1];
    const float* qnn_w  = (const float*)d_in[2];
    const float* out_w  = (const float*)d_in[3];
    const float* out_b  = (const float*)d_in[4];
    float* out = (float*)d_out;

    int B = in_sizes[0] / FDIM;              // 8192
    int pblocks = (B + 7) / 8;               // 1024: proj, 128 thr, 2 elems/warp
    int cblocks = (B + 3) / 4;               // 2048: circuit, 64 thr, 2 warps x 2 elems
    proj_kernel<<<pblocks, PTHREADS>>>(x, proj_w, qnn_w, B);
    circuit_kernel<<<cblocks, CTHREADS>>>(out_w, out_b, out, B);
}

// round 14
// speedup vs baseline: 1.1001x; 1.1001x over previous
#include <cuda_runtime.h>
#include <cstdint>

#define FULL_MASK 0xFFFFFFFFu
#define NQ 8
#define DEPTH 3
#define FDIM 512
#define NCLS 10
#define BTHREADS 128

typedef unsigned long long u64;

// ---- packed f32x2 helpers (sm_100+: FFMA2/FADD2/FMUL2) ----
__device__ __forceinline__ u64 pk2(float lo, float hi) {
    u64 r; asm("mov.b64 %0,{%1,%2};" : "=l"(r) : "f"(lo), "f"(hi)); return r;
}
__device__ __forceinline__ void up2(u64 v, float& lo, float& hi) {
    asm("mov.b64 {%0,%1},%2;" : "=f"(lo), "=f"(hi) : "l"(v));
}
__device__ __forceinline__ u64 fma2_(u64 a, u64 b, u64 c) {
    u64 d; asm("fma.rn.f32x2 %0,%1,%2,%3;" : "=l"(d) : "l"(a), "l"(b), "l"(c)); return d;
}
__device__ __forceinline__ u64 mul2_(u64 a, u64 b) {
    u64 d; asm("mul.rn.f32x2 %0,%1,%2;" : "=l"(d) : "l"(a), "l"(b)); return d;
}
__device__ __forceinline__ u64 add2_(u64 a, u64 b) {
    u64 d; asm("add.rn.f32x2 %0,%1,%2;" : "=l"(d) : "l"(a), "l"(b)); return d;
}
__device__ __forceinline__ u64 neg2_(u64 a) { return a ^ 0x8000000080000000ULL; }
__device__ __forceinline__ u64 bc2(float c) { return pk2(c, c); }

// Deferred-CNOT masks (GF(2)); layout p = (lane<<3)|r, r = qubit bits 0..2.
// parity table for 3-bit values: 0x96
template<int PM, int W>
__device__ __forceinline__ void gateP(u64 AR[8], u64 AI[8], float4 A, float4 Bv, int lane)
{
    constexpr int pr = PM & 7, pl = PM >> 3, wr = W & 7, wl = W >> 3;
    bool bL = (wl != 0) && ((__popc(lane & wl) & 1) != 0);
    u64 oAx2 = bc2(bL ? Bv.z : A.x), oAy2 = bc2(bL ? Bv.w : A.y);
    u64 pAx2 = bc2(bL ? Bv.x : A.z), pAy2 = bc2(bL ? Bv.y : A.w);
    u64 oBx2 = bc2(bL ? A.x : Bv.z), oBy2 = bc2(bL ? A.y : Bv.w);
    u64 pBx2 = bc2(bL ? A.z : Bv.x), pBy2 = bc2(bL ? A.w : Bv.y);

    if constexpr (pl == 0) {
        #pragma unroll
        for (int r = 0; r < 8; r++) {
            if (((0x96 >> (r & wr)) & 1) == 0) {
                const int r1 = r ^ pr;
                u64 a0r = AR[r], a0i = AI[r], a1r = AR[r1], a1i = AI[r1];
                AR[r]  = fma2_(neg2_(pAy2), a1i, fma2_(pAx2, a1r, fma2_(neg2_(oAy2), a0i, mul2_(oAx2, a0r))));
                AI[r]  = fma2_(pAy2, a1r, fma2_(pAx2, a1i, fma2_(oAy2, a0r, mul2_(oAx2, a0i))));
                AR[r1] = fma2_(neg2_(pBy2), a0i, fma2_(pBx2, a0r, fma2_(neg2_(oBy2), a1i, mul2_(oBx2, a1r))));
                AI[r1] = fma2_(pBy2, a0r, fma2_(pBx2, a0i, fma2_(oBy2, a1r, mul2_(oBx2, a1i))));
            }
        }
    } else if constexpr (pr == 0) {
        #pragma unroll
        for (int r = 0; r < 8; r++) {
            u64 tr = __shfl_xor_sync(FULL_MASK, AR[r], pl);
            u64 ti = __shfl_xor_sync(FULL_MASK, AI[r], pl);
            const bool pb = ((0x96 >> (r & wr)) & 1) != 0;
            u64 ox = pb ? oBx2 : oAx2, oy = pb ? oBy2 : oAy2;
            u64 px = pb ? pBx2 : pAx2, py = pb ? pBy2 : pAy2;
            u64 nr = fma2_(neg2_(py), ti, fma2_(px, tr, fma2_(neg2_(oy), AI[r], mul2_(ox, AR[r]))));
            u64 ni = fma2_(py, tr, fma2_(px, ti, fma2_(oy, AR[r], mul2_(ox, AI[r]))));
            AR[r] = nr; AI[r] = ni;
        }
    } else {
        #pragma unroll
        for (int r = 0; r < 8; r++) {
            if (r < (r ^ pr)) {
                const int r1 = r ^ pr;
                u64 sr0 = __shfl_xor_sync(FULL_MASK, AR[r1], pl);
                u64 si0 = __shfl_xor_sync(FULL_MASK, AI[r1], pl);
                u64 sr1 = __shfl_xor_sync(FULL_MASK, AR[r],  pl);
                u64 si1 = __shfl_xor_sync(FULL_MASK, AI[r],  pl);
                const bool pb0 = ((0x96 >> (r  & wr)) & 1) != 0;
                const bool pb1 = ((0x96 >> (r1 & wr)) & 1) != 0;
                u64 o0x = pb0?oBx2:oAx2, o0y = pb0?oBy2:oAy2;
                u64 p0x = pb0?pBx2:pAx2, p0y = pb0?pBy2:pAy2;
                u64 o1x = pb1?oBx2:oAx2, o1y = pb1?oBy2:oAy2;
                u64 p1x = pb1?pBx2:pAx2, p1y = pb1?pBy2:pAy2;
                u64 nr0 = fma2_(neg2_(p0y), si0, fma2_(p0x, sr0, fma2_(neg2_(o0y), AI[r],  mul2_(o0x, AR[r]))));
                u64 ni0 = fma2_(p0y,  sr0, fma2_(p0x, si0, fma2_(o0y,  AR[r],  mul2_(o0x, AI[r]))));
                u64 nr1 = fma2_(neg2_(p1y), si1, fma2_(p1x, sr1, fma2_(neg2_(o1y), AI[r1], mul2_(o1x, AR[r1]))));
                u64 ni1 = fma2_(p1y,  sr1, fma2_(p1x, si1, fma2_(o1y,  AR[r1], mul2_(o1x, AI[r1]))));
                AR[r] = nr0; AI[r] = ni0; AR[r1] = nr1; AI[r1] = ni1;
            }
        }
    }
}

__global__ void __launch_bounds__(BTHREADS, 8) qiskit_head_kernel(
    const float* __restrict__ x,       // (B, 512)
    const float* __restrict__ proj_w,  // (8, 512)
    const float* __restrict__ qnn_w,   // (72,)
    const float* __restrict__ out_w,   // (10, 8)
    const float* __restrict__ out_b,   // (10,)
    float* __restrict__ out,           // (B, 10)
    int B)
{
    __shared__ float4 s_g4[DEPTH * NQ][2];   // 768 B (only smem)
    __shared__ float  s_ow[NCLS * NQ];
    __shared__ float  s_ob[NCLS];

    const int tid  = threadIdx.x;
    const int lane = tid & 31;
    const int warp = tid >> 5;

    if (tid < NCLS * NQ) s_ow[tid] = out_w[tid];
    if (tid < NCLS)      s_ob[tid] = out_b[tid];
    if (tid < DEPTH * NQ) {
        float w0 = qnn_w[tid * 3 + 0];
        float w1 = qnn_w[tid * 3 + 1];
        float w2 = qnn_w[tid * 3 + 2];
        float c0, s0, c1, s1, c2, s2;
        sincosf(0.5f * w0, &s0, &c0);
        sincosf(0.5f * w1, &s1, &c1);
        sincosf(0.5f * w2, &s2, &c2);
        float2 A00 = { c1 * c0,  s1 * s0};
        float2 A01 = {-s1 * c0, -c1 * s0};
        float2 A10 = { s1 * c0, -c1 * s0};
        float2 A11 = { c1 * c0, -s1 * s0};
        float2 g00 = make_float2(c2 * A00.x + s2 * A10.y, c2 * A00.y - s2 * A10.x);
        float2 g01 = make_float2(c2 * A01.x + s2 * A11.y, c2 * A01.y - s2 * A11.x);
        float2 g10 = make_float2(c2 * A10.x + s2 * A00.y, c2 * A10.y - s2 * A00.x);
        float2 g11 = make_float2(c2 * A11.x + s2 * A01.y, c2 * A11.y - s2 * A01.x);
        s_g4[tid][0] = make_float4(g00.x, g00.y, g01.x, g01.y);
        s_g4[tid][1] = make_float4(g10.x, g10.y, g11.x, g11.y);
    }
    __syncthreads();

    auto mrgP = [&](u64 a, u64 b, int dist) -> u64 {
        u64 c = (lane & dist) ? b : a;
        u64 d = (lane & dist) ? a : b;
        return add2_(c, __shfl_xor_sync(FULL_MASK, d, dist));
    };
    auto srcLane = [](int q) { return ((q & 1) << 4) | (((q >> 1) & 1) << 3) | (((q >> 2) & 1) << 2); };

    const int b0 = (blockIdx.x * 4 + warp) * 2;   // elem A (lo half)
    const int b1 = b0 + 1;                        // elem B (hi half)
    if (b0 >= B) return;
    const bool v1 = (b1 < B);

    // ---- projection: direct __ldg of proj_w (L1 broadcast, no staging) ----
    float acc[2][NQ];
    #pragma unroll
    for (int e = 0; e < 2; e++)
        #pragma unroll
        for (int q = 0; q < NQ; q++) acc[e][q] = 0.f;

    const float4* xr0 = (const float4*)(x + (size_t)b0 * FDIM);
    const float4* xr1 = (const float4*)(x + (size_t)(v1 ? b1 : b0) * FDIM);
    #pragma unroll
    for (int ch = 0; ch < 4; ch++) {
        float4 xv0 = xr0[ch * 32 + lane];
        float4 xv1 = xr1[ch * 32 + lane];
        #pragma unroll
        for (int q = 0; q < NQ; q++) {
            float4 wv = __ldg((const float4*)&proj_w[q * FDIM + ch * 128 + lane * 4]);
            acc[0][q] += xv0.x*wv.x + xv0.y*wv.y + xv0.z*wv.z + xv0.w*wv.w;
            acc[1][q] += xv1.x*wv.x + xv1.y*wv.y + xv1.z*wv.z + xv1.w*wv.w;
        }
    }
    u64 CV, SV;
    {
        u64 ap[8];
        #pragma unroll
        for (int q = 0; q < NQ; q++) ap[q] = pk2(acc[0][q], acc[1][q]);
        u64 m0 = mrgP(ap[0], ap[1], 16), m1 = mrgP(ap[2], ap[3], 16);
        u64 m2 = mrgP(ap[4], ap[5], 16), m3 = mrgP(ap[6], ap[7], 16);
        u64 n0 = mrgP(m0, m1, 8), n1 = mrgP(m2, m3, 8);
        u64 F  = mrgP(n0, n1, 4);
        F = add2_(F, __shfl_xor_sync(FULL_MASK, F, 2));
        F = add2_(F, __shfl_xor_sync(FULL_MASK, F, 1));
        float dA, dB; up2(F, dA, dB);
        float hA = tanhf(dA) * 0.78539816339744830962f;
        float hB = tanhf(dB) * 0.78539816339744830962f;
        float cA, sA, cB, sB;
        __sincosf(hA, &sA, &cA);
        __sincosf(hB, &sB, &cB);
        CV = pk2(cA, cB); SV = pk2(sA, sB);
    }

    // ---- state after encoding + layer-0 gates: product state (packed) ----
    u64 Lr = pk2(1.f, 1.f), Li = 0ULL;
    #pragma unroll
    for (int k = 0; k < 5; k++) {
        const int q = k + 3;
        u64 cq = __shfl_sync(FULL_MASK, CV, srcLane(q));
        u64 sq = __shfl_sync(FULL_MASK, SV, srcLane(q));
        float4 V = s_g4[q][(lane >> k) & 1];
        u64 wx = fma2_(bc2(V.z), sq, mul2_(bc2(V.x), cq));
        u64 wy = fma2_(bc2(V.w), sq, mul2_(bc2(V.y), cq));
        u64 nLr = fma2_(neg2_(Li), wy, mul2_(Lr, wx));
        u64 nLi = fma2_(Li, wx, mul2_(Lr, wy));
        Lr = nLr; Li = nLi;
    }
    u64 AR[8], AI[8];
    {
        u64 cq = __shfl_sync(FULL_MASK, CV, srcLane(0));
        u64 sq = __shfl_sync(FULL_MASK, SV, srcLane(0));
        float4 A0 = s_g4[0][0], B0 = s_g4[0][1];
        u64 a0x = fma2_(bc2(A0.z), sq, mul2_(bc2(A0.x), cq));
        u64 a0y = fma2_(bc2(A0.w), sq, mul2_(bc2(A0.y), cq));
        u64 b0x = fma2_(bc2(B0.z), sq, mul2_(bc2(B0.x), cq));
        u64 b0y = fma2_(bc2(B0.w), sq, mul2_(bc2(B0.y), cq));
        AR[0] = fma2_(neg2_(Li), a0y, mul2_(Lr, a0x));  AI[0] = fma2_(Li, a0x, mul2_(Lr, a0y));
        AR[1] = fma2_(neg2_(Li), b0y, mul2_(Lr, b0x));  AI[1] = fma2_(Li, b0x, mul2_(Lr, b0y));
    }
    {
        u64 cq = __shfl_sync(FULL_MASK, CV, srcLane(1));
        u64 sq = __shfl_sync(FULL_MASK, SV, srcLane(1));
        float4 A1 = s_g4[1][0], B1 = s_g4[1][1];
        u64 a1x = fma2_(bc2(A1.z), sq, mul2_(bc2(A1.x), cq));
        u64 a1y = fma2_(bc2(A1.w), sq, mul2_(bc2(A1.y), cq));
        u64 b1x = fma2_(bc2(B1.z), sq, mul2_(bc2(B1.x), cq));
        u64 b1y = fma2_(bc2(B1.w), sq, mul2_(bc2(B1.y), cq));
        #pragma unroll
        for (int r = 0; r < 2; r++) {
            u64 tr = AR[r], ti = AI[r];
            AR[r + 2] = fma2_(neg2_(b1y), ti, mul2_(tr, b1x));  AI[r + 2] = fma2_(b1y, tr, mul2_(ti, b1x));
            AR[r]     = fma2_(neg2_(a1y), ti, mul2_(tr, a1x));  AI[r]     = fma2_(a1y, tr, mul2_(ti, a1x));
        }
    }
    {
        u64 cq = __shfl_sync(FULL_MASK, CV, srcLane(2));
        u64 sq = __shfl_sync(FULL_MASK, SV, srcLane(2));
        float4 A2 = s_g4[2][0], B2 = s_g4[2][1];
        u64 a2x = fma2_(bc2(A2.z), sq, mul2_(bc2(A2.x), cq));
        u64 a2y = fma2_(bc2(A2.w), sq, mul2_(bc2(A2.y), cq));
        u64 b2x = fma2_(bc2(B2.z), sq, mul2_(bc2(B2.x), cq));
        u64 b2y = fma2_(bc2(B2.w), sq, mul2_(bc2(B2.y), cq));
        #pragma unroll
        for (int r = 0; r < 4; r++) {
            u64 tr = AR[r], ti = AI[r];
            AR[r + 4] = fma2_(neg2_(b2y), ti, mul2_(tr, b2x));  AI[r + 4] = fma2_(b2y, tr, mul2_(ti, b2x));
            AR[r]     = fma2_(neg2_(a2y), ti, mul2_(tr, a2x));  AI[r]     = fma2_(a2y, tr, mul2_(ti, a2x));
        }
    }

    // ---- layers 1,2 with deferred-CNOT masks (packed 2 elems) ----
    #define GATE(idx, PMv, Wv) gateP<PMv, Wv>(AR, AI, s_g4[idx][0], s_g4[idx][1], lane)
    // layer 1 (phi = C)
    GATE(8,  0x03, 0xFE); GATE(9,  0x06, 0x03); GATE(10, 0x0C, 0x07); GATE(11, 0x18, 0x0F);
    GATE(12, 0x30, 0x1F); GATE(13, 0x60, 0x3F); GATE(14, 0xC0, 0x7F); GATE(15, 0x83, 0xFF);
    // layer 2 (phi = C^2)
    GATE(16, 0x05, 0xAB); GATE(17, 0x0A, 0xFD); GATE(18, 0x14, 0xFA); GATE(19, 0x28, 0xF5);
    GATE(20, 0x50, 0xEA); GATE(21, 0xA0, 0xD5); GATE(22, 0x43, 0xAA); GATE(23, 0x86, 0x55);
    #undef GATE

    // ---- PauliZ via Walsh-Hadamard of |amp|^2 (phi = C^3), packed ----
    u64 S[8];
    #pragma unroll
    for (int r = 0; r < 8; r++) S[r] = fma2_(AI[r], AI[r], mul2_(AR[r], AR[r]));
    #pragma unroll
    for (int st = 0; st < 3; st++) {
        const int d = 1 << st;
        #pragma unroll
        for (int r = 0; r < 8; r++) {
            if (!(r & d)) {
                u64 a = add2_(S[r], S[r + d]);
                u64 b = add2_(S[r], neg2_(S[r + d]));
                S[r] = a; S[r + d] = b;
            }
        }
    }
    auto sgp = [&](int wl, u64 v) -> u64 { return (__popc(lane & wl) & 1) ? neg2_(v) : v; };
    u64 z0 = sgp(0x06, S[2]), z1 = sgp(0x0A, S[6]);
    u64 z2 = sgp(0x15, S[4]), z3 = sgp(0x0B, S[1]);
    u64 z4 = sgp(0x16, S[3]), z5 = sgp(0x0C, S[6]);
    u64 z6 = sgp(0x19, S[4]), z7 = sgp(0x13, S[1]);
    u64 m0 = mrgP(z0, z1, 16), m1 = mrgP(z2, z3, 16);
    u64 m2 = mrgP(z4, z5, 16), m3 = mrgP(z6, z7, 16);
    u64 n0 = mrgP(m0, m1, 8),  n1 = mrgP(m2, m3, 8);
    u64 F  = mrgP(n0, n1, 4);
    F = add2_(F, __shfl_xor_sync(FULL_MASK, F, 2));
    F = add2_(F, __shfl_xor_sync(FULL_MASK, F, 1));
    u64 gq[NQ];
    #pragma unroll
    for (int q = 0; q < NQ; q++) gq[q] = __shfl_sync(FULL_MASK, F, srcLane(q));

    // ---- output head ----
    if (lane < NCLS) {
        float o0 = s_ob[lane], o1 = o0;
        #pragma unroll
        for (int q = 0; q < NQ; q++) {
            float w = s_ow[lane * NQ + q];
            float gA, gB; up2(gq[q], gA, gB);
            o0 += gA * w;
            o1 += gB * w;
        }
        out[(size_t)b0 * NCLS + lane] = o0;
        if (v1) out[(size_t)b1 * NCLS + lane] = o1;
    }
}

extern "C" void kernel_launch(void* const* d_in, const int* in_sizes, int n_in,
                              void* d_out, int out_size) {
    const float* x      = (const float*)d_in[0];
    const float* proj_w = (const float*)d_in[1];
    const float* qnn_w  = (const float*)d_in[2];
    const float* out_w  = (const float*)d_in[3];
    const float* out_b  = (const float*)d_in[4];
    float* out = (float*)d_out;

    int B = in_sizes[0] / FDIM;            // 8192
    int blocks = (B + 7) / 8;              // 1024 blocks x 4 warps x 2 packed elems
    qiskit_head_kernel<<<blocks, BTHREADS>>>(x, proj_w, qnn_w, out_w, out_b, out, B);
}